// round 3
// baseline (speedup 1.0000x reference)
#include <cuda_runtime.h>

typedef unsigned long long u64;

#define THREADS 256
#define NATOM   128
#define KNB     127
#define NBATCH  64
#define BT      4

// ---- shared memory float offsets ----
#define OFF_TY   0        // 128 ints
#define OFF_W0   128      // [e][25]
#define OFF_B0   228
#define OFF_W1   328      // [e][i25][o52]
#define E1STR    1300
#define OFF_B1   5528     // [e][52]
#define OFF_W2   5736     // [e][i50][m104]
#define E2STR    5200
#define OFF_B2   26536    // [e][104]
#define OFF_CS   26952    // [3][128]
#define OFF_EA   27336    // [3][128]
#define OFF_H1   27720    // [256][51]
#define H1STR    51
#define OFF_G    40776    // [127][101]
#define GSTR     101
#define OFF_UP   53603    // [3][104]
#define OFF_US   53915    // [3][104]
#define OFF_CNT  54227    // 4 ints
#define OFF_ST   54231    // 5 ints
#define OFF_WS   54236    // 5 ints
#define OFF_SIDX 54241    // 128 ints
#define SMEM_FLOATS 54369
#define SMEM_BYTES (SMEM_FLOATS * 4)

__device__ __forceinline__ float tanh_fast(float x) {
    float e = __expf(2.0f * x);
    return 1.0f - __fdividef(2.0f, e + 1.0f);
}
__device__ __forceinline__ u64 pack2(float lo, float hi) {
    u64 r; asm("mov.b64 %0, {%1, %2};" : "=l"(r) : "f"(lo), "f"(hi)); return r;
}
__device__ __forceinline__ float2 unpack2(u64 v) {
    float2 r; asm("mov.b64 {%0, %1}, %2;" : "=f"(r.x), "=f"(r.y) : "l"(v)); return r;
}
__device__ __forceinline__ u64 fma2(u64 a, u64 b, u64 c) {
    u64 r; asm("fma.rn.f32x2 %0, %1, %2, %3;" : "=l"(r) : "l"(a), "l"(b), "l"(c)); return r;
}

extern __shared__ float sm[];

__global__ void __launch_bounds__(THREADS, 1)
feat_kernel(const float* __restrict__ coords, const int* __restrict__ types,
            const float* __restrict__ W0g, const float* __restrict__ B0g,
            const float* __restrict__ W1g, const float* __restrict__ B1g,
            const float* __restrict__ W2g, const float* __restrict__ B2g,
            float* __restrict__ out)
{
    const int n    = blockIdx.x;
    const int tid  = threadIdx.x;
    const int warp = tid >> 5;
    const int lane = tid & 31;
    int* smi = (int*)sm;

    const int eb = types[n] * 4;

    // zero weight+bias region (covers all pads)
    for (int i = OFF_W0 + tid; i < OFF_CS; i += THREADS) sm[i] = 0.0f;
    if (tid < 128) smi[OFF_TY + tid] = types[tid];
    __syncthreads();

    // ---- stage transposed weights for this atom's 4 sub-types ----
    for (int i = tid; i < 100; i += THREADS) {
        sm[OFF_W0 + i] = W0g[eb * 25 + i];
        sm[OFF_B0 + i] = B0g[eb * 25 + i];
    }
    for (int idx = tid; idx < 4 * 50 * 25; idx += THREADS) {
        int i = idx % 25, o = (idx / 25) % 50, e = idx / 1250;
        sm[OFF_W1 + e * E1STR + i * 52 + o] = W1g[(eb + e) * 1250 + o * 25 + i];
    }
    for (int idx = tid; idx < 200; idx += THREADS) {
        int o = idx % 50, e = idx / 50;
        sm[OFF_B1 + e * 52 + o] = B1g[(eb + e) * 50 + o];
    }
    for (int idx = tid; idx < 4 * 100 * 50; idx += THREADS) {
        int i = idx % 50, m = (idx / 50) % 100, e = idx / 5000;
        sm[OFF_W2 + e * E2STR + i * 104 + m] = W2g[(eb + e) * 5000 + m * 50 + i];
    }
    for (int idx = tid; idx < 400; idx += THREADS) {
        int m = idx % 100, e = idx / 100;
        sm[OFF_B2 + e * 104 + m] = B2g[(eb + e) * 100 + m];
    }

    // ---- per-type neighbor grouping (types fixed; once per block) ----
    if (tid < 4) {
        int c = 0;
        for (int j2 = 0; j2 < 128; j2++)
            if (j2 != n && smi[OFF_TY + j2] == tid) c++;
        smi[OFF_CNT + tid] = c;
    }
    __syncthreads();
    if (tid == 0) {
        int s = 0, w = 0;
        #pragma unroll
        for (int e = 0; e < 4; e++) {
            smi[OFF_ST + e] = s;
            smi[OFF_WS + e] = w;
            s += smi[OFF_CNT + e];
            w += (smi[OFF_CNT + e] + 31) >> 5;
        }
        smi[OFF_ST + 4] = s;
        smi[OFF_WS + 4] = w;
    }
    __syncthreads();
    if (tid < 128 && tid != n) {
        int t = smi[OFF_TY + tid];
        int r = 0;
        for (int j2 = 0; j2 < tid; j2++)
            if (j2 != n && smi[OFF_TY + j2] == t) r++;
        smi[OFF_SIDX + smi[OFF_ST + t] + r] = tid;
    }
    __syncthreads();

    // my warp's type group (warp-uniform e -> broadcast weight loads)
    int my_e = -1, slot = 0;
    bool active = false;
    #pragma unroll
    for (int e = 0; e < 4; e++) {
        int w0 = smi[OFF_WS + e], w1 = smi[OFF_WS + e + 1];
        if (warp >= w0 && warp < w1) {
            my_e = e;
            slot = smi[OFF_ST + e] + ((warp - w0) << 5) + lane;
            active = slot < smi[OFF_ST + e] + smi[OFF_CNT + e];
        }
    }
    const int e = (my_e >= 0) ? my_e : 0;
    const int j = active ? smi[OFF_SIDX + slot] : n;

    const float* w0e = sm + OFF_W0 + e * 25;
    const float* b0e = sm + OFF_B0 + e * 25;
    const float* w1e = sm + OFF_W1 + e * E1STR;
    const float* b1e = sm + OFF_B1 + e * 52;
    const float* w2e = sm + OFF_W2 + e * E2STR;
    const float* b2e = sm + OFF_B2 + e * 104;
    float* h1row = sm + OFF_H1 + tid * H1STR;
    float* grow  = sm + OFF_G  + slot * GSTR;

    for (int bi = 0; bi < BT; bi++) {
        const int b = blockIdx.y * BT + bi;
        __syncthreads();
        {
            const float* cb = coords + (size_t)b * (NATOM * 3);
            for (int i = tid; i < NATOM * 3; i += THREADS)
                sm[OFF_CS + (i % 3) * NATOM + (i / 3)] = cb[i];
        }
        __syncthreads();

        if (my_e >= 0) {
            float rx = sm[OFF_CS + n]       - sm[OFF_CS + j];
            float ry = sm[OFF_CS + 128 + n] - sm[OFF_CS + 128 + j];
            float rz = sm[OFF_CS + 256 + n] - sm[OFF_CS + 256 + j];
            float d2 = rx * rx + ry * ry + rz * rz;
            float dinv = rsqrtf(d2);
            float di2  = dinv * dinv;
            if (active) {
                sm[OFF_EA + slot]       = rx * di2;
                sm[OFF_EA + 128 + slot] = ry * di2;
                sm[OFF_EA + 256 + slot] = rz * di2;
            }
            const float x = dinv;

            // ---- layer1 (layer0 fused into i-loop), acc in regs ----
            u64 acc1[26];
            #pragma unroll
            for (int t = 0; t < 13; t++) {
                ulonglong2 bb = *(const ulonglong2*)(b1e + t * 4);
                acc1[2*t] = bb.x; acc1[2*t+1] = bb.y;
            }
            #pragma unroll 5
            for (int i = 0; i < 25; i++) {
                float h = tanh_fast(fmaf(x, w0e[i], b0e[i]));
                u64 hd = pack2(h, h);
                const float* wp = w1e + i * 52;
                #pragma unroll
                for (int t = 0; t < 13; t++) {
                    ulonglong2 w = *(const ulonglong2*)(wp + t * 4);
                    acc1[2*t]   = fma2(w.x, hd, acc1[2*t]);
                    acc1[2*t+1] = fma2(w.y, hd, acc1[2*t+1]);
                }
            }
            // epilogue: recompute h0 (compile-time idx) for residuals
            float h0v[25];
            #pragma unroll
            for (int c = 0; c < 25; c++)
                h0v[c] = tanh_fast(fmaf(x, w0e[c], b0e[c]));
            #pragma unroll
            for (int t = 0; t < 25; t++) {
                float2 v = unpack2(acc1[t]);
                int o = 2 * t;
                h1row[o]   = tanh_fast(v.x) + h0v[(o   < 25) ? o   : o - 25];
                h1row[o+1] = tanh_fast(v.y) + h0v[(o+1 < 25) ? o+1 : o+1 - 25];
            }

            // ---- layer2: all 100 outputs in regs, broadcast weights ----
            u64 acc2[52];
            #pragma unroll
            for (int t = 0; t < 26; t++) {
                ulonglong2 bb = *(const ulonglong2*)(b2e + t * 4);
                acc2[2*t] = bb.x; acc2[2*t+1] = bb.y;
            }
            #pragma unroll 2
            for (int i = 0; i < 50; i++) {
                float h = h1row[i];
                u64 hd = pack2(h, h);
                const float* wp = w2e + i * 104;
                #pragma unroll
                for (int t = 0; t < 26; t++) {
                    ulonglong2 w = *(const ulonglong2*)(wp + t * 4);
                    acc2[2*t]   = fma2(w.x, hd, acc2[2*t]);
                    acc2[2*t+1] = fma2(w.y, hd, acc2[2*t+1]);
                }
            }
            #pragma unroll
            for (int q = 0; q < 50; q++) {
                float2 v = unpack2(acc2[q]);
                int m = 2 * q;
                float g0 = tanh_fast(v.x) + h1row[(m   < 50) ? m   : m - 50];
                float g1 = tanh_fast(v.y) + h1row[(m+1 < 50) ? m+1 : m+1 - 50];
                if (active) { grow[m] = g0; grow[m+1] = g1; }
            }
        }
        __syncthreads();

        // ---- U[c][m] = sum_k ea[c][k] * G[k][m]; split k over halves ----
        const int m    = tid & 127;
        const int half = tid >> 7;
        float u0 = 0.0f, u1 = 0.0f, u2 = 0.0f;
        if (m < 100) {
            const int kb = half ? 64 : 0;
            const int ke = half ? KNB : 64;
            const float* gp = sm + OFF_G + m;
            #pragma unroll 4
            for (int kk = kb; kk < ke; kk++) {
                float g = gp[kk * GSTR];
                u0 = fmaf(sm[OFF_EA + kk],       g, u0);
                u1 = fmaf(sm[OFF_EA + 128 + kk], g, u1);
                u2 = fmaf(sm[OFF_EA + 256 + kk], g, u2);
            }
            if (half) {
                sm[OFF_UP + m]       = u0;
                sm[OFF_UP + 104 + m] = u1;
                sm[OFF_UP + 208 + m] = u2;
            }
        }
        __syncthreads();
        if (!half && m < 100) {
            u0 += sm[OFF_UP + m];
            u1 += sm[OFF_UP + 104 + m];
            u2 += sm[OFF_UP + 208 + m];
            sm[OFF_US + m]       = u0;
            sm[OFF_US + 104 + m] = u1;
            sm[OFF_US + 208 + m] = u2;
        }
        __syncthreads();
        if (!half && m < 100) {
            float4 r;
            r.x = u0 * sm[OFF_US + 0] + u1 * sm[OFF_US + 104 + 0] + u2 * sm[OFF_US + 208 + 0];
            r.y = u0 * sm[OFF_US + 1] + u1 * sm[OFF_US + 104 + 1] + u2 * sm[OFF_US + 208 + 1];
            r.z = u0 * sm[OFF_US + 2] + u1 * sm[OFF_US + 104 + 2] + u2 * sm[OFF_US + 208 + 2];
            r.w = u0 * sm[OFF_US + 3] + u1 * sm[OFF_US + 104 + 3] + u2 * sm[OFF_US + 208 + 3];
            *(float4*)(out + ((size_t)b * NATOM + n) * 400 + m * 4) = r;
        }
    }
}

extern "C" void kernel_launch(void* const* d_in, const int* in_sizes, int n_in,
                              void* d_out, int out_size)
{
    (void)in_sizes; (void)n_in; (void)out_size;
    const float* coords = (const float*)d_in[0];
    const int*   types  = (const int*)d_in[1];
    const float* W0g = (const float*)d_in[2];
    const float* B0g = (const float*)d_in[3];
    const float* W1g = (const float*)d_in[4];
    const float* B1g = (const float*)d_in[5];
    const float* W2g = (const float*)d_in[6];
    const float* B2g = (const float*)d_in[7];
    float* out = (float*)d_out;

    cudaFuncSetAttribute(feat_kernel, cudaFuncAttributeMaxDynamicSharedMemorySize, SMEM_BYTES);

    dim3 grid(NATOM, NBATCH / BT);   // (128, 16)
    feat_kernel<<<grid, THREADS, SMEM_BYTES>>>(coords, types,
                                               W0g, B0g, W1g, B1g, W2g, B2g, out);
}

// round 5
// speedup vs baseline: 1.1064x; 1.1064x over previous
#include <cuda_runtime.h>

typedef unsigned long long u64;

#define THREADS 512
#define NATOM   128
#define KNB     127
#define NBATCH  64
#define BT      4

// ---- shared memory float offsets ----
#define OFF_TY   0        // 128 ints
#define OFF_W0   128      // [e][25]
#define OFF_B0   228      // [e][25]
#define OFF_W1   328      // [e][i25][56]  (o0..24, pad3, o25..49, pad3)
#define E1STR    1400
#define OFF_B1   5928     // [e][56]
#define OFF_W2   6152     // [e][i50][104] (m0..49, pad2, m50..99, pad2)
#define E2STR    5200
#define OFF_B2   26952    // [e][104]
#define OFF_CS   27368    // [3][128]
#define OFF_EA   27752    // [3][128]
#define OFF_H1   28136    // [127][51]
#define H1STR    51
#define OFF_G    34613    // [127][101]
#define GSTR     101
#define OFF_UP   47440    // [4][3][104]
#define OFF_US   48688    // [3][104]
#define OFF_CNT  49000    // 4 ints
#define OFF_ST   49004    // 5 ints
#define OFF_WS   49009    // 5 ints
#define OFF_SIDX 49014    // 128 ints
#define SMEM_FLOATS 49142
#define SMEM_BYTES (SMEM_FLOATS * 4)

__device__ __forceinline__ float tanhx(float x) {
    float y; asm("tanh.approx.f32 %0, %1;" : "=f"(y) : "f"(x)); return y;
}
__device__ __forceinline__ u64 pack2(float lo, float hi) {
    u64 r; asm("mov.b64 %0, {%1, %2};" : "=l"(r) : "f"(lo), "f"(hi)); return r;
}
__device__ __forceinline__ float2 unpack2(u64 v) {
    float2 r; asm("mov.b64 {%0, %1}, %2;" : "=f"(r.x), "=f"(r.y) : "l"(v)); return r;
}
__device__ __forceinline__ u64 fma2(u64 a, u64 b, u64 c) {
    u64 r; asm("fma.rn.f32x2 %0, %1, %2, %3;" : "=l"(r) : "l"(a), "l"(b), "l"(c)); return r;
}

extern __shared__ float sm[];

__global__ void __launch_bounds__(THREADS, 1)
feat_kernel(const float* __restrict__ coords, const int* __restrict__ types,
            const float* __restrict__ W0g, const float* __restrict__ B0g,
            const float* __restrict__ W1g, const float* __restrict__ B1g,
            const float* __restrict__ W2g, const float* __restrict__ B2g,
            float* __restrict__ out)
{
    const int n    = blockIdx.x;
    const int tid  = threadIdx.x;
    const int warp = tid >> 5;
    const int lane = tid & 31;
    const int gw   = warp & 7;    // group-warp id (mirrored across halves)
    const int half = warp >> 3;   // 0: outputs low half, 1: high half
    int* smi = (int*)sm;

    const int eb = types[n] * 4;

    // zero weight+bias region (covers all pads)
    for (int i = OFF_W0 + tid; i < OFF_CS; i += THREADS) sm[i] = 0.0f;
    if (tid < 128) smi[OFF_TY + tid] = types[tid];
    __syncthreads();

    // ---- stage transposed weights for this atom's 4 sub-types ----
    for (int i = tid; i < 100; i += THREADS) {
        sm[OFF_W0 + i] = W0g[eb * 25 + i];
        sm[OFF_B0 + i] = B0g[eb * 25 + i];
    }
    for (int idx = tid; idx < 4 * 50 * 25; idx += THREADS) {
        int i = idx % 25, o = (idx / 25) % 50, e = idx / 1250;
        int pos = (o < 25) ? o : o + 3;
        sm[OFF_W1 + e * E1STR + i * 56 + pos] = W1g[(eb + e) * 1250 + o * 25 + i];
    }
    for (int idx = tid; idx < 200; idx += THREADS) {
        int o = idx % 50, e = idx / 50;
        int pos = (o < 25) ? o : o + 3;
        sm[OFF_B1 + e * 56 + pos] = B1g[(eb + e) * 50 + o];
    }
    for (int idx = tid; idx < 4 * 100 * 50; idx += THREADS) {
        int i = idx % 50, m = (idx / 50) % 100, e = idx / 5000;
        int pos = (m < 50) ? m : m + 2;
        sm[OFF_W2 + e * E2STR + i * 104 + pos] = W2g[(eb + e) * 5000 + m * 50 + i];
    }
    for (int idx = tid; idx < 400; idx += THREADS) {
        int m = idx % 100, e = idx / 100;
        int pos = (m < 50) ? m : m + 2;
        sm[OFF_B2 + e * 104 + pos] = B2g[(eb + e) * 100 + m];
    }

    // ---- per-type neighbor grouping (types fixed; once per block) ----
    if (tid < 4) {
        int c = 0;
        for (int j2 = 0; j2 < 128; j2++)
            if (j2 != n && smi[OFF_TY + j2] == tid) c++;
        smi[OFF_CNT + tid] = c;
    }
    __syncthreads();
    if (tid == 0) {
        int s = 0, w = 0;
        #pragma unroll
        for (int e = 0; e < 4; e++) {
            smi[OFF_ST + e] = s;
            smi[OFF_WS + e] = w;
            s += smi[OFF_CNT + e];
            w += (smi[OFF_CNT + e] + 31) >> 5;
        }
        smi[OFF_ST + 4] = s;
        smi[OFF_WS + 4] = w;
    }
    __syncthreads();
    if (tid < 128 && tid != n) {
        int t = smi[OFF_TY + tid];
        int r = 0;
        for (int j2 = 0; j2 < tid; j2++)
            if (j2 != n && smi[OFF_TY + j2] == t) r++;
        smi[OFF_SIDX + smi[OFF_ST + t] + r] = tid;
    }
    __syncthreads();

    // warp-uniform type group
    int my_e = -1, slot = 0;
    bool active = false;
    #pragma unroll
    for (int e = 0; e < 4; e++) {
        int w0 = smi[OFF_WS + e], w1 = smi[OFF_WS + e + 1];
        if (gw >= w0 && gw < w1) {
            my_e = e;
            slot = smi[OFF_ST + e] + ((gw - w0) << 5) + lane;
            active = slot < smi[OFF_ST + e] + smi[OFF_CNT + e];
        }
    }
    const int e = (my_e >= 0) ? my_e : 0;
    const int j = active ? smi[OFF_SIDX + slot] : n;

    const float* w0e = sm + OFF_W0 + e * 25;
    const float* b0e = sm + OFF_B0 + e * 25;
    const float* w1e = sm + OFF_W1 + e * E1STR + half * 28;  // half's 28-slice
    const float* b1e = sm + OFF_B1 + e * 56 + half * 28;
    const float* w2e = sm + OFF_W2 + e * E2STR + half * 52;  // half's 52-slice
    const float* b2e = sm + OFF_B2 + e * 104 + half * 52;
    float* h1row = sm + OFF_H1 + slot * H1STR;   // write own half, read full
    float* grow  = sm + OFF_G  + slot * GSTR + half * 50;

    for (int bi = 0; bi < BT; bi++) {
        const int b = blockIdx.y * BT + bi;
        __syncthreads();
        {
            const float* cb = coords + (size_t)b * (NATOM * 3);
            for (int i = tid; i < NATOM * 3; i += THREADS)
                sm[OFF_CS + (i % 3) * NATOM + (i / 3)] = cb[i];
        }
        __syncthreads();

        if (my_e >= 0) {
            float rx = sm[OFF_CS + n]       - sm[OFF_CS + j];
            float ry = sm[OFF_CS + 128 + n] - sm[OFF_CS + 128 + j];
            float rz = sm[OFF_CS + 256 + n] - sm[OFF_CS + 256 + j];
            float d2 = rx * rx + ry * ry + rz * rz;
            float dinv = rsqrtf(d2);
            float di2  = dinv * dinv;
            if (active && half == 0) {
                sm[OFF_EA + slot]       = rx * di2;
                sm[OFF_EA + 128 + slot] = ry * di2;
                sm[OFF_EA + 256 + slot] = rz * di2;
            }
            const float x = dinv;

            // ---- layer0: full h0 in registers ----
            float h0v[25];
            #pragma unroll
            for (int i = 0; i < 25; i++)
                h0v[i] = tanhx(fmaf(x, w0e[i], b0e[i]));

            // ---- layer1: this half's 25 outputs (28 padded) ----
            u64 acc1[14];
            #pragma unroll
            for (int t = 0; t < 7; t++) {
                ulonglong2 bb = *(const ulonglong2*)(b1e + t * 4);
                acc1[2*t] = bb.x; acc1[2*t+1] = bb.y;
            }
            #pragma unroll
            for (int i = 0; i < 25; i++) {
                u64 hd = pack2(h0v[i], h0v[i]);
                const float* wp = w1e + i * 56;
                #pragma unroll
                for (int t = 0; t < 7; t++) {
                    ulonglong2 w = *(const ulonglong2*)(wp + t * 4);
                    acc1[2*t]   = fma2(w.x, hd, acc1[2*t]);
                    acc1[2*t+1] = fma2(w.y, hd, acc1[2*t+1]);
                }
            }
            if (active) {
                // residual: global o = half*25 + oo, h0[(half*25+oo) mod 25] = h0[oo]
                #pragma unroll
                for (int q = 0; q < 13; q++) {
                    float2 v = unpack2(acc1[q]);
                    int oo = 2 * q;
                    if (oo   < 25) h1row[half * 25 + oo]   = tanhx(v.x) + h0v[oo];
                    if (oo+1 < 25) h1row[half * 25 + oo+1] = tanhx(v.y) + h0v[oo+1];
                }
            }
        }
        __syncthreads();

        if (my_e >= 0 && active) {
            // ---- layer2: this half's 50 outputs (52 padded) ----
            u64 acc2[26];
            #pragma unroll
            for (int t = 0; t < 13; t++) {
                ulonglong2 bb = *(const ulonglong2*)(b2e + t * 4);
                acc2[2*t] = bb.x; acc2[2*t+1] = bb.y;
            }
            #pragma unroll 2
            for (int i = 0; i < 50; i++) {
                float h = h1row[i];
                u64 hd = pack2(h, h);
                const float* wp = w2e + i * 104;
                #pragma unroll
                for (int t = 0; t < 13; t++) {
                    ulonglong2 w = *(const ulonglong2*)(wp + t * 4);
                    acc2[2*t]   = fma2(w.x, hd, acc2[2*t]);
                    acc2[2*t+1] = fma2(w.y, hd, acc2[2*t+1]);
                }
            }
            // residual: global m = half*50 + mm, h1[(half*50+mm) mod 50] = h1[mm]
            #pragma unroll
            for (int q = 0; q < 25; q++) {
                float2 v = unpack2(acc2[q]);
                int mm = 2 * q;
                grow[mm]   = tanhx(v.x) + h1row[mm];
                grow[mm+1] = tanhx(v.y) + h1row[mm+1];
            }
        }
        __syncthreads();

        // ---- U[c][m] = sum_k ea[c][k]*G[k][m]; 4 k-quarters ----
        const int m = tid & 127;
        const int q = tid >> 7;
        float u0 = 0.0f, u1 = 0.0f, u2 = 0.0f;
        if (m < 100) {
            const int kb = q * 32;
            const int ke = (q == 3) ? KNB : kb + 32;
            const float* gp = sm + OFF_G + m;
            #pragma unroll 4
            for (int kk = kb; kk < ke; kk++) {
                float g = gp[kk * GSTR];
                u0 = fmaf(sm[OFF_EA + kk],       g, u0);
                u1 = fmaf(sm[OFF_EA + 128 + kk], g, u1);
                u2 = fmaf(sm[OFF_EA + 256 + kk], g, u2);
            }
            sm[OFF_UP + q * 312 + m]       = u0;
            sm[OFF_UP + q * 312 + 104 + m] = u1;
            sm[OFF_UP + q * 312 + 208 + m] = u2;
        }
        __syncthreads();
        if (tid < 128 && m < 100) {
            u0 = sm[OFF_UP + m]       + sm[OFF_UP + 312 + m]
               + sm[OFF_UP + 624 + m] + sm[OFF_UP + 936 + m];
            u1 = sm[OFF_UP + 104 + m]       + sm[OFF_UP + 312 + 104 + m]
               + sm[OFF_UP + 624 + 104 + m] + sm[OFF_UP + 936 + 104 + m];
            u2 = sm[OFF_UP + 208 + m]       + sm[OFF_UP + 312 + 208 + m]
               + sm[OFF_UP + 624 + 208 + m] + sm[OFF_UP + 936 + 208 + m];
            sm[OFF_US + m]       = u0;
            sm[OFF_US + 104 + m] = u1;
            sm[OFF_US + 208 + m] = u2;
        }
        __syncthreads();
        if (tid < 128 && m < 100) {
            float4 r;
            r.x = u0 * sm[OFF_US + 0] + u1 * sm[OFF_US + 104 + 0] + u2 * sm[OFF_US + 208 + 0];
            r.y = u0 * sm[OFF_US + 1] + u1 * sm[OFF_US + 104 + 1] + u2 * sm[OFF_US + 208 + 1];
            r.z = u0 * sm[OFF_US + 2] + u1 * sm[OFF_US + 104 + 2] + u2 * sm[OFF_US + 208 + 2];
            r.w = u0 * sm[OFF_US + 3] + u1 * sm[OFF_US + 104 + 3] + u2 * sm[OFF_US + 208 + 3];
            *(float4*)(out + ((size_t)b * NATOM + n) * 400 + m * 4) = r;
        }
    }
}

extern "C" void kernel_launch(void* const* d_in, const int* in_sizes, int n_in,
                              void* d_out, int out_size)
{
    (void)in_sizes; (void)n_in; (void)out_size;
    const float* coords = (const float*)d_in[0];
    const int*   types  = (const int*)d_in[1];
    const float* W0g = (const float*)d_in[2];
    const float* B0g = (const float*)d_in[3];
    const float* W1g = (const float*)d_in[4];
    const float* B1g = (const float*)d_in[5];
    const float* W2g = (const float*)d_in[6];
    const float* B2g = (const float*)d_in[7];
    float* out = (float*)d_out;

    cudaFuncSetAttribute(feat_kernel, cudaFuncAttributeMaxDynamicSharedMemorySize, SMEM_BYTES);

    dim3 grid(NATOM, NBATCH / BT);   // (128, 16)
    feat_kernel<<<grid, THREADS, SMEM_BYTES>>>(coords, types,
                                               W0g, B0g, W1g, B1g, W2g, B2g, out);
}

// round 6
// speedup vs baseline: 1.1935x; 1.0788x over previous
#include <cuda_runtime.h>

typedef unsigned long long u64;

#define THREADS 1024
#define NATOM   128
#define KNB     127
#define NBATCH  64
#define BT      8

// ---- shared memory float offsets ----
#define OFF_TY   0        // 128 ints
#define OFF_W0   128      // [e][25]
#define OFF_B0   228      // [e][25]
#define OFF_W1   328      // [e][i25][64]  quarter tiles of 16 (13,13,12,12 real)
#define E1STR    1600
#define OFF_B1   6728     // [e][64]
#define OFF_W2   6984     // [e][i50][112] quarter tiles of 28 (25 real each)
#define E2STR    5600
#define OFF_B2   29384    // [e][112]
#define OFF_CS   29832    // [3][128]
#define OFF_EA   30216    // [3][128]
#define OFF_H1   30600    // [127][51]
#define H1STR    51
#define OFF_G    37077    // [127][101]
#define GSTR     101
#define OFF_UP   49904    // [8][3][104]
#define OFF_US   52400    // [3][104]
#define OFF_CNT  52712    // 4 ints
#define OFF_ST   52716    // 5 ints
#define OFF_WS   52721    // 5 ints
#define OFF_SIDX 52726    // 128 ints
#define SMEM_FLOATS 52854
#define SMEM_BYTES (SMEM_FLOATS * 4)

__device__ __forceinline__ float tanhx(float x) {
    float y; asm("tanh.approx.f32 %0, %1;" : "=f"(y) : "f"(x)); return y;
}
__device__ __forceinline__ u64 pack2(float lo, float hi) {
    u64 r; asm("mov.b64 %0, {%1, %2};" : "=l"(r) : "f"(lo), "f"(hi)); return r;
}
__device__ __forceinline__ float2 unpack2(u64 v) {
    float2 r; asm("mov.b64 {%0, %1}, %2;" : "=f"(r.x), "=f"(r.y) : "l"(v)); return r;
}
__device__ __forceinline__ u64 fma2(u64 a, u64 b, u64 c) {
    u64 r; asm("fma.rn.f32x2 %0, %1, %2, %3;" : "=l"(r) : "l"(a), "l"(b), "l"(c)); return r;
}

extern __shared__ float sm[];

__global__ void __launch_bounds__(THREADS, 1)
feat_kernel(const float* __restrict__ coords, const int* __restrict__ types,
            const float* __restrict__ W0g, const float* __restrict__ B0g,
            const float* __restrict__ W1g, const float* __restrict__ B1g,
            const float* __restrict__ W2g, const float* __restrict__ B2g,
            float* __restrict__ out)
{
    const int n    = blockIdx.x;
    const int tid  = threadIdx.x;
    const int warp = tid >> 5;
    const int lane = tid & 31;
    const int gw   = warp & 7;    // group-warp id (mirrored across quarters)
    const int qt   = warp >> 3;   // output quarter 0..3
    int* smi = (int*)sm;

    const int eb = types[n] * 4;

    // zero weight+bias region (covers all pads)
    for (int i = OFF_W0 + tid; i < OFF_CS; i += THREADS) sm[i] = 0.0f;
    if (tid < 128) smi[OFF_TY + tid] = types[tid];
    __syncthreads();

    // ---- stage transposed weights for this atom's 4 sub-types ----
    for (int i = tid; i < 100; i += THREADS) {
        sm[OFF_W0 + i] = W0g[eb * 25 + i];
        sm[OFF_B0 + i] = B0g[eb * 25 + i];
    }
    // layer1: quarter tiles of 16 at offsets 0/16/32/48; real o-quarters 13,13,12,12
    for (int idx = tid; idx < 4 * 50 * 25; idx += THREADS) {
        int i = idx % 25, o = (idx / 25) % 50, e = idx / 1250;
        int pos = (o < 13) ? o : (o < 26) ? o + 3 : (o < 38) ? o + 6 : o + 10;
        sm[OFF_W1 + e * E1STR + i * 64 + pos] = W1g[(eb + e) * 1250 + o * 25 + i];
    }
    for (int idx = tid; idx < 200; idx += THREADS) {
        int o = idx % 50, e = idx / 50;
        int pos = (o < 13) ? o : (o < 26) ? o + 3 : (o < 38) ? o + 6 : o + 10;
        sm[OFF_B1 + e * 64 + pos] = B1g[(eb + e) * 50 + o];
    }
    // layer2: quarter tiles of 28 at offsets 0/28/56/84; real m-quarters 25 each
    for (int idx = tid; idx < 4 * 100 * 50; idx += THREADS) {
        int i = idx % 50, m = (idx / 50) % 100, e = idx / 5000;
        int pos = m + 3 * (m / 25);
        sm[OFF_W2 + e * E2STR + i * 112 + pos] = W2g[(eb + e) * 5000 + m * 50 + i];
    }
    for (int idx = tid; idx < 448; idx += THREADS) {
        int m = idx % 112, e = idx / 112;
        if (m < 100)
            sm[OFF_B2 + e * 112 + m + 3 * (m / 25)] = B2g[(eb + e) * 100 + m];
    }

    // ---- per-type neighbor grouping (types fixed; once per block) ----
    if (tid < 4) {
        int c = 0;
        for (int j2 = 0; j2 < 128; j2++)
            if (j2 != n && smi[OFF_TY + j2] == tid) c++;
        smi[OFF_CNT + tid] = c;
    }
    __syncthreads();
    if (tid == 0) {
        int s = 0, w = 0;
        #pragma unroll
        for (int e = 0; e < 4; e++) {
            smi[OFF_ST + e] = s;
            smi[OFF_WS + e] = w;
            s += smi[OFF_CNT + e];
            w += (smi[OFF_CNT + e] + 31) >> 5;
        }
        smi[OFF_ST + 4] = s;
        smi[OFF_WS + 4] = w;
    }
    __syncthreads();
    if (tid < 128 && tid != n) {
        int t = smi[OFF_TY + tid];
        int r = 0;
        for (int j2 = 0; j2 < tid; j2++)
            if (j2 != n && smi[OFF_TY + j2] == t) r++;
        smi[OFF_SIDX + smi[OFF_ST + t] + r] = tid;
    }
    __syncthreads();

    // warp-uniform type group
    int my_e = -1, slot = 0;
    bool active = false;
    #pragma unroll
    for (int e = 0; e < 4; e++) {
        int w0 = smi[OFF_WS + e], w1 = smi[OFF_WS + e + 1];
        if (gw >= w0 && gw < w1) {
            my_e = e;
            slot = smi[OFF_ST + e] + ((gw - w0) << 5) + lane;
            active = slot < smi[OFF_ST + e] + smi[OFF_CNT + e];
        }
    }
    const int e = (my_e >= 0) ? my_e : 0;
    const int j = active ? smi[OFF_SIDX + slot] : n;

    const float* w0e = sm + OFF_W0 + e * 25;
    const float* b0e = sm + OFF_B0 + e * 25;
    const float* w1q = sm + OFF_W1 + e * E1STR + 16 * qt;
    const float* b1q = sm + OFF_B1 + e * 64 + 16 * qt;
    const float* w2q = sm + OFF_W2 + e * E2STR + 28 * qt;
    const float* b2q = sm + OFF_B2 + e * 112 + 28 * qt;
    const int sz1   = (qt < 2) ? 13 : 12;
    const int base1 = (qt < 2) ? 13 * qt : 12 * qt + 2;   // 0,13,26,38
    float* h1row = sm + OFF_H1 + slot * H1STR;
    float* h1w   = h1row + base1;
    float* grow  = sm + OFF_G + slot * GSTR + 25 * qt;

    for (int bi = 0; bi < BT; bi++) {
        const int b = blockIdx.y * BT + bi;
        __syncthreads();
        {
            const float* cb = coords + (size_t)b * (NATOM * 3);
            for (int i = tid; i < NATOM * 3; i += THREADS)
                sm[OFF_CS + (i % 3) * NATOM + (i / 3)] = cb[i];
        }
        __syncthreads();

        float x = 0.0f;
        if (active) {
            float rx = sm[OFF_CS + n]       - sm[OFF_CS + j];
            float ry = sm[OFF_CS + 128 + n] - sm[OFF_CS + 128 + j];
            float rz = sm[OFF_CS + 256 + n] - sm[OFF_CS + 256 + j];
            float d2 = rx * rx + ry * ry + rz * rz;
            float dinv = rsqrtf(d2);
            float di2  = dinv * dinv;
            if (qt == 0) {
                sm[OFF_EA + slot]       = rx * di2;
                sm[OFF_EA + 128 + slot] = ry * di2;
                sm[OFF_EA + 256 + slot] = rz * di2;
            }
            x = dinv;

            // ---- layer0 fused + layer1 quarter (16 padded outputs) ----
            u64 acc1[8];
            #pragma unroll
            for (int t = 0; t < 4; t++) {
                ulonglong2 bb = *(const ulonglong2*)(b1q + t * 4);
                acc1[2*t] = bb.x; acc1[2*t+1] = bb.y;
            }
            #pragma unroll
            for (int i = 0; i < 25; i++) {
                float h = tanhx(fmaf(x, w0e[i], b0e[i]));
                u64 hd = pack2(h, h);
                const float* wp = w1q + i * 64;
                #pragma unroll
                for (int t = 0; t < 4; t++) {
                    ulonglong2 w = *(const ulonglong2*)(wp + t * 4);
                    acc1[2*t]   = fma2(w.x, hd, acc1[2*t]);
                    acc1[2*t+1] = fma2(w.y, hd, acc1[2*t+1]);
                }
            }
            // residual h0[(base1+l) mod 25] recomputed from smem (broadcast)
            #pragma unroll
            for (int q = 0; q < 7; q++) {
                float2 v = unpack2(acc1[q]);
                int l0 = 2 * q, l1 = 2 * q + 1;
                if (l0 < sz1) {
                    int r = base1 + l0; if (r >= 25) r -= 25;
                    h1w[l0] = tanhx(v.x) + tanhx(fmaf(x, w0e[r], b0e[r]));
                }
                if (l1 < sz1) {
                    int r = base1 + l1; if (r >= 25) r -= 25;
                    h1w[l1] = tanhx(v.y) + tanhx(fmaf(x, w0e[r], b0e[r]));
                }
            }
        }
        __syncthreads();

        if (active) {
            // ---- layer2 quarter: 25 outputs (28 padded) ----
            u64 acc2[14];
            #pragma unroll
            for (int t = 0; t < 7; t++) {
                ulonglong2 bb = *(const ulonglong2*)(b2q + t * 4);
                acc2[2*t] = bb.x; acc2[2*t+1] = bb.y;
            }
            #pragma unroll 5
            for (int i = 0; i < 50; i++) {
                float h = h1row[i];
                u64 hd = pack2(h, h);
                const float* wp = w2q + i * 112;
                #pragma unroll
                for (int t = 0; t < 7; t++) {
                    ulonglong2 w = *(const ulonglong2*)(wp + t * 4);
                    acc2[2*t]   = fma2(w.x, hd, acc2[2*t]);
                    acc2[2*t+1] = fma2(w.y, hd, acc2[2*t+1]);
                }
            }
            // residual: m = 25*qt + l -> h1[(m) mod 50] = h1[l + 25*(qt&1)]
            const float* h1res = h1row + 25 * (qt & 1);
            #pragma unroll
            for (int q = 0; q < 13; q++) {
                float2 v = unpack2(acc2[q]);
                int l0 = 2 * q, l1 = 2 * q + 1;
                if (l0 < 25) grow[l0] = tanhx(v.x) + h1res[l0];
                if (l1 < 25) grow[l1] = tanhx(v.y) + h1res[l1];
            }
        }
        __syncthreads();

        // ---- U[c][m] = sum_k ea[c][k]*G[k][m]; 8 k-chunks of 16 ----
        const int m  = tid & 127;
        const int kq = tid >> 7;
        float u0 = 0.0f, u1 = 0.0f, u2 = 0.0f;
        if (m < 100) {
            const int kb = kq * 16;
            const int ke = (kq == 7) ? KNB : kb + 16;
            const float* gp = sm + OFF_G + m;
            #pragma unroll 4
            for (int kk = kb; kk < ke; kk++) {
                float g = gp[kk * GSTR];
                u0 = fmaf(sm[OFF_EA + kk],       g, u0);
                u1 = fmaf(sm[OFF_EA + 128 + kk], g, u1);
                u2 = fmaf(sm[OFF_EA + 256 + kk], g, u2);
            }
            sm[OFF_UP + kq * 312 + m]       = u0;
            sm[OFF_UP + kq * 312 + 104 + m] = u1;
            sm[OFF_UP + kq * 312 + 208 + m] = u2;
        }
        __syncthreads();
        if (tid < 128 && m < 100) {
            u0 = u1 = u2 = 0.0f;
            #pragma unroll
            for (int qq = 0; qq < 8; qq++) {
                u0 += sm[OFF_UP + qq * 312 + m];
                u1 += sm[OFF_UP + qq * 312 + 104 + m];
                u2 += sm[OFF_UP + qq * 312 + 208 + m];
            }
            sm[OFF_US + m]       = u0;
            sm[OFF_US + 104 + m] = u1;
            sm[OFF_US + 208 + m] = u2;
        }
        __syncthreads();
        if (tid < 128 && m < 100) {
            float4 r;
            r.x = u0 * sm[OFF_US + 0] + u1 * sm[OFF_US + 104 + 0] + u2 * sm[OFF_US + 208 + 0];
            r.y = u0 * sm[OFF_US + 1] + u1 * sm[OFF_US + 104 + 1] + u2 * sm[OFF_US + 208 + 1];
            r.z = u0 * sm[OFF_US + 2] + u1 * sm[OFF_US + 104 + 2] + u2 * sm[OFF_US + 208 + 2];
            r.w = u0 * sm[OFF_US + 3] + u1 * sm[OFF_US + 104 + 3] + u2 * sm[OFF_US + 208 + 3];
            *(float4*)(out + ((size_t)b * NATOM + n) * 400 + m * 4) = r;
        }
    }
}

extern "C" void kernel_launch(void* const* d_in, const int* in_sizes, int n_in,
                              void* d_out, int out_size)
{
    (void)in_sizes; (void)n_in; (void)out_size;
    const float* coords = (const float*)d_in[0];
    const int*   types  = (const int*)d_in[1];
    const float* W0g = (const float*)d_in[2];
    const float* B0g = (const float*)d_in[3];
    const float* W1g = (const float*)d_in[4];
    const float* B1g = (const float*)d_in[5];
    const float* W2g = (const float*)d_in[6];
    const float* B2g = (const float*)d_in[7];
    float* out = (float*)d_out;

    cudaFuncSetAttribute(feat_kernel, cudaFuncAttributeMaxDynamicSharedMemorySize, SMEM_BYTES);

    dim3 grid(NATOM, NBATCH / BT);   // (128, 8)
    feat_kernel<<<grid, THREADS, SMEM_BYTES>>>(coords, types,
                                               W0g, B0g, W1g, B1g, W2g, B2g, out);
}

// round 7
// speedup vs baseline: 1.9498x; 1.6336x over previous
#include <cuda_runtime.h>

typedef unsigned long long u64;

#define THREADS 512
#define NATOM   128
#define KNB     127
#define NBATCH  64
#define BT      8

// ---- shared memory float offsets (all e-strides == 8 mod 32 banks) ----
#define OFF_TY   0        // 128 ints
#define OFF_W0   128      // [e*40 + o]           160
#define OFF_B0   288      //                      160
#define OFF_W1   448      // [e*1608 + i*64 + pos] 6432 (tiles 16 @ 0/16/32/48; 13,13,12,12)
#define E1STR    1608
#define OFF_B1   6880     // [e*72 + pos]          288
#define OFF_W2   7168     // [e*5608 + i*112 + pos] 22432 (tiles 28 @ 0/28/56/84; 25 each)
#define E2STR    5608
#define OFF_B2   29600    // [e*136 + pos]         544
#define OFF_CS   30144    // [bb][3][128]          768
#define OFF_EA   30912    // [bb][k*4+c]           1024
#define OFF_H0   31936    // [bb][slot*27 + r]     6858
#define H0BUF    3429
#define OFF_X    38794    // h1: [bb*6477 + slot*51 + o] / G: [slot*101 + m]   12954
#define H1BUF    6477
#define GSTR     101
#define OFF_UP   51748    // [kq*312 + c*104 + m]  1248
#define OFF_US   52996    //                       312
#define OFF_SIDX 53308    // 128 ints
#define OFF_CNT  53436    // 4
#define OFF_ST   53440    // 5
#define SMEM_FLOATS 53448
#define SMEM_BYTES (SMEM_FLOATS * 4)

__device__ __forceinline__ float tanhx(float x) {
    float y; asm("tanh.approx.f32 %0, %1;" : "=f"(y) : "f"(x)); return y;
}
__device__ __forceinline__ u64 pack2(float lo, float hi) {
    u64 r; asm("mov.b64 %0, {%1, %2};" : "=l"(r) : "f"(lo), "f"(hi)); return r;
}
__device__ __forceinline__ float2 unpack2(u64 v) {
    float2 r; asm("mov.b64 {%0, %1}, %2;" : "=f"(r.x), "=f"(r.y) : "l"(v)); return r;
}
__device__ __forceinline__ u64 fma2(u64 a, u64 b, u64 c) {
    u64 r; asm("fma.rn.f32x2 %0, %1, %2, %3;" : "=l"(r) : "l"(a), "l"(b), "l"(c)); return r;
}
#define BARG(id) asm volatile("bar.sync %0, 128;" :: "r"(id) : "memory")

extern __shared__ float sm[];

__global__ void __launch_bounds__(THREADS, 1)
feat_kernel(const float* __restrict__ coords, const int* __restrict__ types,
            const float* __restrict__ W0g, const float* __restrict__ B0g,
            const float* __restrict__ W1g, const float* __restrict__ B1g,
            const float* __restrict__ W2g, const float* __restrict__ B2g,
            float* __restrict__ out)
{
    const int n    = blockIdx.x;
    const int tid  = threadIdx.x;
    const int warp = tid >> 5;
    const int lane = tid & 31;
    const int pw   = warp & 3;    // pair-warp: covers sorted slots [32pw, 32pw+32)
    const int qt   = warp >> 2;   // output quarter 0..3
    int* smi = (int*)sm;

    const int eb = types[n] * 4;

    // zero weight+bias region (covers all pads)
    for (int i = OFF_W0 + tid; i < OFF_CS; i += THREADS) sm[i] = 0.0f;
    if (tid < 128) smi[OFF_TY + tid] = types[tid];
    __syncthreads();

    // ---- stage weights (transposed) for this atom's 4 sub-types ----
    for (int i = tid; i < 100; i += THREADS) {
        int o = i % 25, e = i / 25;
        sm[OFF_W0 + e * 40 + o] = W0g[(eb + e) * 25 + o];
        sm[OFF_B0 + e * 40 + o] = B0g[(eb + e) * 25 + o];
    }
    for (int idx = tid; idx < 4 * 50 * 25; idx += THREADS) {
        int i = idx % 25, o = (idx / 25) % 50, e = idx / 1250;
        int pos = (o < 13) ? o : (o < 26) ? o + 3 : (o < 38) ? o + 6 : o + 10;
        sm[OFF_W1 + e * E1STR + i * 64 + pos] = W1g[(eb + e) * 1250 + o * 25 + i];
    }
    for (int idx = tid; idx < 200; idx += THREADS) {
        int o = idx % 50, e = idx / 50;
        int pos = (o < 13) ? o : (o < 26) ? o + 3 : (o < 38) ? o + 6 : o + 10;
        sm[OFF_B1 + e * 72 + pos] = B1g[(eb + e) * 50 + o];
    }
    for (int idx = tid; idx < 4 * 100 * 50; idx += THREADS) {
        int i = idx % 50, m = (idx / 50) % 100, e = idx / 5000;
        int pos = m + 3 * (m / 25);
        sm[OFF_W2 + e * E2STR + i * 112 + pos] = W2g[(eb + e) * 5000 + m * 50 + i];
    }
    for (int idx = tid; idx < 400; idx += THREADS) {
        int m = idx % 100, e = idx / 100;
        int pos = m + 3 * (m / 25);
        sm[OFF_B2 + e * 136 + pos] = B2g[(eb + e) * 100 + m];
    }

    // ---- sort neighbors by type (stable) ----
    if (tid < 4) {
        int c = 0;
        for (int j2 = 0; j2 < 128; j2++)
            if (j2 != n && smi[OFF_TY + j2] == tid) c++;
        smi[OFF_CNT + tid] = c;
    }
    __syncthreads();
    if (tid == 0) {
        int s = 0;
        #pragma unroll
        for (int e = 0; e < 4; e++) { smi[OFF_ST + e] = s; s += smi[OFF_CNT + e]; }
        smi[OFF_ST + 4] = s;
    }
    __syncthreads();
    if (tid < 128 && tid != n) {
        int t = smi[OFF_TY + tid];
        int r = 0;
        for (int j2 = 0; j2 < tid; j2++)
            if (j2 != n && smi[OFF_TY + j2] == t) r++;
        smi[OFF_SIDX + smi[OFF_ST + t] + r] = tid;
    }
    __syncthreads();

    const int  slot   = (pw << 5) + lane;         // 0..127; 127 idle
    const bool active = slot < KNB;
    const int  j = active ? smi[OFF_SIDX + slot] : n;
    const int  e = active ? smi[OFF_TY + j] : 0;

    const float* w0e = sm + OFF_W0 + e * 40;
    const float* b0e = sm + OFF_B0 + e * 40;
    const float* w1q = sm + OFF_W1 + e * E1STR + 16 * qt;
    const float* b1q = sm + OFF_B1 + e * 72 + 16 * qt;
    const float* w2q = sm + OFF_W2 + e * E2STR + 28 * qt;
    const float* b2q = sm + OFF_B2 + e * 136 + 28 * qt;
    const int sz1    = (qt < 2) ? 13 : 12;
    const int tbase1 = (qt < 2) ? 13 * qt : 12 * qt + 2;   // 0,13,26,38
    const int base0  = (qt == 0) ? 0 : 1 + 6 * qt;         // 0,7,13,19
    const int cnt0   = (qt == 0) ? 7 : 6;
    float* h0a = sm + OFF_H0 + slot * 27;
    float* h0b = h0a + H0BUF;
    float* h1a = sm + OFF_X + slot * 51;
    float* h1b = h1a + H1BUF;
    const int barid = 1 + pw;

    for (int bi2 = 0; bi2 < BT / 2; bi2++) {
        const int b0i = blockIdx.y * BT + bi2 * 2;
        __syncthreads();   // X / EA / CS reuse guard
        for (int i = tid; i < 2 * 384; i += THREADS) {
            int bb = i / 384, ii = i % 384;
            sm[OFF_CS + bb * 384 + (ii % 3) * 128 + ii / 3] =
                coords[(size_t)(b0i + bb) * 384 + ii];
        }
        __syncthreads();

        float xa = 0.0f, xb = 0.0f;
        if (active) {
            #pragma unroll
            for (int bb = 0; bb < 2; bb++) {
                const float* cs = sm + OFF_CS + bb * 384;
                float rx = cs[n]       - cs[j];
                float ry = cs[128 + n] - cs[128 + j];
                float rz = cs[256 + n] - cs[256 + j];
                float dinv = rsqrtf(rx * rx + ry * ry + rz * rz);
                float di2 = dinv * dinv;
                if (qt == 0) {
                    float* ea = sm + OFF_EA + bb * 512 + slot * 4;
                    ea[0] = rx * di2; ea[1] = ry * di2; ea[2] = rz * di2; ea[3] = 0.0f;
                }
                if (bb == 0) xa = dinv; else xb = dinv;
            }
            // h0 split across co-warps: qt computes cnt0 entries at base0
            for (int c = 0; c < cnt0; c++) {
                int r = base0 + c;
                float w = w0e[r], bi = b0e[r];
                h0a[r] = tanhx(fmaf(xa, w, bi));
                h0b[r] = tanhx(fmaf(xb, w, bi));
            }
        }
        BARG(barid);   // h0 ready within co-group

        // ---- layer1: quarter outputs, 2 batches ----
        {
            u64 acc[2][8];
            #pragma unroll
            for (int t = 0; t < 4; t++) {
                ulonglong2 bb = *(const ulonglong2*)(b1q + t * 4);
                acc[0][2*t] = bb.x; acc[0][2*t+1] = bb.y;
                acc[1][2*t] = bb.x; acc[1][2*t+1] = bb.y;
            }
            #pragma unroll 5
            for (int i = 0; i < 25; i++) {
                u64 hda = pack2(h0a[i], h0a[i]);
                u64 hdb = pack2(h0b[i], h0b[i]);
                const float* wp = w1q + i * 64;
                #pragma unroll
                for (int t = 0; t < 4; t++) {
                    ulonglong2 w = *(const ulonglong2*)(wp + t * 4);
                    acc[0][2*t]   = fma2(w.x, hda, acc[0][2*t]);
                    acc[0][2*t+1] = fma2(w.y, hda, acc[0][2*t+1]);
                    acc[1][2*t]   = fma2(w.x, hdb, acc[1][2*t]);
                    acc[1][2*t+1] = fma2(w.y, hdb, acc[1][2*t+1]);
                }
            }
            if (active) {
                #pragma unroll
                for (int q = 0; q < 7; q++) {
                    float2 va = unpack2(acc[0][q]);
                    float2 vb = unpack2(acc[1][q]);
                    int l0 = 2 * q, l1 = 2 * q + 1;
                    if (l0 < sz1) {
                        int o = tbase1 + l0, r = (o < 25) ? o : o - 25;
                        h1a[o] = tanhx(va.x) + h0a[r];
                        h1b[o] = tanhx(vb.x) + h0b[r];
                    }
                    if (l1 < sz1) {
                        int o = tbase1 + l1, r = (o < 25) ? o : o - 25;
                        h1a[o] = tanhx(va.y) + h0a[r];
                        h1b[o] = tanhx(vb.y) + h0b[r];
                    }
                }
            }
        }
        BARG(barid);   // h1 ready within co-group

        // ---- layer2: quarter (25 outs), 2 batches; G kept in registers ----
        float ga[25], gb[25];
        {
            u64 acc[2][14];
            #pragma unroll
            for (int t = 0; t < 7; t++) {
                ulonglong2 bb = *(const ulonglong2*)(b2q + t * 4);
                acc[0][2*t] = bb.x; acc[0][2*t+1] = bb.y;
                acc[1][2*t] = bb.x; acc[1][2*t+1] = bb.y;
            }
            #pragma unroll 5
            for (int i = 0; i < 50; i++) {
                u64 hda = pack2(h1a[i], h1a[i]);
                u64 hdb = pack2(h1b[i], h1b[i]);
                const float* wp = w2q + i * 112;
                #pragma unroll
                for (int t = 0; t < 7; t++) {
                    ulonglong2 w = *(const ulonglong2*)(wp + t * 4);
                    acc[0][2*t]   = fma2(w.x, hda, acc[0][2*t]);
                    acc[0][2*t+1] = fma2(w.y, hda, acc[0][2*t+1]);
                    acc[1][2*t]   = fma2(w.x, hdb, acc[1][2*t]);
                    acc[1][2*t+1] = fma2(w.y, hdb, acc[1][2*t+1]);
                }
            }
            // residual: m = 25*qt + l -> h1[(25*qt+l) mod 50] = h1[l + 25*(qt&1)]
            const int roff = 25 * (qt & 1);
            #pragma unroll
            for (int q = 0; q < 13; q++) {
                float2 va = unpack2(acc[0][q]);
                float2 vb = unpack2(acc[1][q]);
                int l0 = 2 * q, l1 = 2 * q + 1;
                if (l0 < 25) { ga[l0] = tanhx(va.x) + h1a[roff + l0];
                               gb[l0] = tanhx(vb.x) + h1b[roff + l0]; }
                if (l1 < 25) { ga[l1] = tanhx(va.y) + h1a[roff + l1];
                               gb[l1] = tanhx(vb.y) + h1b[roff + l1]; }
            }
        }
        __syncthreads();   // all h1 reads done; X region becomes G

        #pragma unroll
        for (int bb = 0; bb < 2; bb++) {
            // store this batch's G (registers -> X region)
            if (active) {
                float* grow = sm + OFF_X + slot * GSTR + 25 * qt;
                #pragma unroll
                for (int l = 0; l < 25; l++) grow[l] = bb ? gb[l] : ga[l];
            }
            __syncthreads();

            // U[c][m] = sum_k ea[c][k]*G[k][m]; 4 k-chunks of 32
            const int m  = tid & 127;
            const int kq = tid >> 7;
            float u0 = 0.0f, u1 = 0.0f, u2 = 0.0f;
            if (m < 100) {
                const int kb = kq * 32;
                const int ke = (kq == 3) ? KNB : kb + 32;
                const float* gp = sm + OFF_X + m;
                const float* ep = sm + OFF_EA + bb * 512;
                #pragma unroll 4
                for (int kk = kb; kk < ke; kk++) {
                    float4 ea = *(const float4*)(ep + kk * 4);
                    float g = gp[kk * GSTR];
                    u0 = fmaf(ea.x, g, u0);
                    u1 = fmaf(ea.y, g, u1);
                    u2 = fmaf(ea.z, g, u2);
                }
                sm[OFF_UP + kq * 312 + m]       = u0;
                sm[OFF_UP + kq * 312 + 104 + m] = u1;
                sm[OFF_UP + kq * 312 + 208 + m] = u2;
            }
            __syncthreads();
            float us0 = 0.0f, us1 = 0.0f, us2 = 0.0f;
            if (tid < 100) {
                #pragma unroll
                for (int qq = 0; qq < 4; qq++) {
                    us0 += sm[OFF_UP + qq * 312 + tid];
                    us1 += sm[OFF_UP + qq * 312 + 104 + tid];
                    us2 += sm[OFF_UP + qq * 312 + 208 + tid];
                }
                sm[OFF_US + tid]       = us0;
                sm[OFF_US + 104 + tid] = us1;
                sm[OFF_US + 208 + tid] = us2;
            }
            __syncthreads();
            if (tid < 100) {
                float4 r;
                r.x = us0 * sm[OFF_US + 0] + us1 * sm[OFF_US + 104 + 0] + us2 * sm[OFF_US + 208 + 0];
                r.y = us0 * sm[OFF_US + 1] + us1 * sm[OFF_US + 104 + 1] + us2 * sm[OFF_US + 208 + 1];
                r.z = us0 * sm[OFF_US + 2] + us1 * sm[OFF_US + 104 + 2] + us2 * sm[OFF_US + 208 + 2];
                r.w = us0 * sm[OFF_US + 3] + us1 * sm[OFF_US + 104 + 3] + us2 * sm[OFF_US + 208 + 3];
                *(float4*)(out + ((size_t)(b0i + bb) * NATOM + n) * 400 + tid * 4) = r;
            }
            __syncthreads();   // G reads done before next batch's stores
        }
    }
}

extern "C" void kernel_launch(void* const* d_in, const int* in_sizes, int n_in,
                              void* d_out, int out_size)
{
    (void)in_sizes; (void)n_in; (void)out_size;
    const float* coords = (const float*)d_in[0];
    const int*   types  = (const int*)d_in[1];
    const float* W0g = (const float*)d_in[2];
    const float* B0g = (const float*)d_in[3];
    const float* W1g = (const float*)d_in[4];
    const float* B1g = (const float*)d_in[5];
    const float* W2g = (const float*)d_in[6];
    const float* B2g = (const float*)d_in[7];
    float* out = (float*)d_out;

    cudaFuncSetAttribute(feat_kernel, cudaFuncAttributeMaxDynamicSharedMemorySize, SMEM_BYTES);

    dim3 grid(NATOM, NBATCH / BT);   // (128, 8)
    feat_kernel<<<grid, THREADS, SMEM_BYTES>>>(coords, types,
                                               W0g, B0g, W1g, B1g, W2g, B2g, out);
}

// round 8
// speedup vs baseline: 2.0362x; 1.0443x over previous
#include <cuda_runtime.h>

typedef unsigned long long u64;

#define THREADS 512
#define NATOM   128
#define KNB     127
#define NBATCH  64
#define BT      8

// ---- shared memory float offsets (all e-strides == 8 mod 32 banks) ----
#define OFF_TY   0        // 128 ints
#define OFF_W0   128      // [e*40 + o]           160
#define OFF_B0   288      //                      160
#define OFF_W1   448      // [e*1608 + i*64 + pos] 6432 (tiles 16 @ 0/16/32/48; 13,13,12,12)
#define E1STR    1608
#define OFF_B1   6880     // [e*72 + pos]          288
#define OFF_W2   7168     // [e*5608 + i*112 + pos] 22432 (tiles 28 @ 0/28/56/84; 25 each)
#define E2STR    5608
#define OFF_B2   29600    // [e*136 + pos]         544
#define OFF_CS   30144    // [bb][3][128]          768
#define OFF_EA   30912    // [bb][k*4+c]           1024
#define OFF_H0   31936    // [bb][slot*27 + r]     6858
#define H0BUF    3429
#define OFF_X    38794    // h1: [bb*6477 + slot*51 + o] / G: [slot*101 + m]   12954
#define H1BUF    6477
#define GSTR     101
#define OFF_UP   51748    // [kq*312 + c*104 + m]  1248
#define OFF_US   52996    //                       312
#define OFF_SIDX 53308    // 128 ints
#define OFF_CNT  53436    // 4
#define OFF_ST   53440    // 5
#define SMEM_FLOATS 53448
#define SMEM_BYTES (SMEM_FLOATS * 4)

__device__ __forceinline__ float tanhx(float x) {
    float y; asm("tanh.approx.f32 %0, %1;" : "=f"(y) : "f"(x)); return y;
}
__device__ __forceinline__ u64 pack2(float lo, float hi) {
    u64 r; asm("mov.b64 %0, {%1, %2};" : "=l"(r) : "f"(lo), "f"(hi)); return r;
}
__device__ __forceinline__ float2 unpack2(u64 v) {
    float2 r; asm("mov.b64 {%0, %1}, %2;" : "=f"(r.x), "=f"(r.y) : "l"(v)); return r;
}
__device__ __forceinline__ u64 fma2(u64 a, u64 b, u64 c) {
    u64 r; asm("fma.rn.f32x2 %0, %1, %2, %3;" : "=l"(r) : "l"(a), "l"(b), "l"(c)); return r;
}
#define BARG(id) asm volatile("bar.sync %0, 128;" :: "r"(id) : "memory")

extern __shared__ float sm[];

__global__ void __launch_bounds__(THREADS, 1)
feat_kernel(const float* __restrict__ coords, const int* __restrict__ types,
            const float* __restrict__ W0g, const float* __restrict__ B0g,
            const float* __restrict__ W1g, const float* __restrict__ B1g,
            const float* __restrict__ W2g, const float* __restrict__ B2g,
            float* __restrict__ out)
{
    const int n    = blockIdx.x;
    const int tid  = threadIdx.x;
    const int warp = tid >> 5;
    const int lane = tid & 31;
    const int pw   = warp & 3;    // pair-warp: covers sorted slots [32pw, 32pw+32)
    const int qt   = warp >> 2;   // output quarter 0..3
    int* smi = (int*)sm;

    const int eb = types[n] * 4;

    // zero weight+bias region (covers all pads)
    for (int i = OFF_W0 + tid; i < OFF_CS; i += THREADS) sm[i] = 0.0f;
    if (tid < 128) smi[OFF_TY + tid] = types[tid];
    __syncthreads();

    // ---- stage weights (transposed) for this atom's 4 sub-types ----
    for (int i = tid; i < 100; i += THREADS) {
        int o = i % 25, e = i / 25;
        sm[OFF_W0 + e * 40 + o] = W0g[(eb + e) * 25 + o];
        sm[OFF_B0 + e * 40 + o] = B0g[(eb + e) * 25 + o];
    }
    for (int idx = tid; idx < 4 * 50 * 25; idx += THREADS) {
        int i = idx % 25, o = (idx / 25) % 50, e = idx / 1250;
        int pos = (o < 13) ? o : (o < 26) ? o + 3 : (o < 38) ? o + 6 : o + 10;
        sm[OFF_W1 + e * E1STR + i * 64 + pos] = W1g[(eb + e) * 1250 + o * 25 + i];
    }
    for (int idx = tid; idx < 200; idx += THREADS) {
        int o = idx % 50, e = idx / 50;
        int pos = (o < 13) ? o : (o < 26) ? o + 3 : (o < 38) ? o + 6 : o + 10;
        sm[OFF_B1 + e * 72 + pos] = B1g[(eb + e) * 50 + o];
    }
    for (int idx = tid; idx < 4 * 100 * 50; idx += THREADS) {
        int i = idx % 50, m = (idx / 50) % 100, e = idx / 5000;
        int pos = m + 3 * (m / 25);
        sm[OFF_W2 + e * E2STR + i * 112 + pos] = W2g[(eb + e) * 5000 + m * 50 + i];
    }
    for (int idx = tid; idx < 400; idx += THREADS) {
        int m = idx % 100, e = idx / 100;
        int pos = m + 3 * (m / 25);
        sm[OFF_B2 + e * 136 + pos] = B2g[(eb + e) * 100 + m];
    }

    // ---- sort neighbors by type (stable) ----
    if (tid < 4) {
        int c = 0;
        for (int j2 = 0; j2 < 128; j2++)
            if (j2 != n && smi[OFF_TY + j2] == tid) c++;
        smi[OFF_CNT + tid] = c;
    }
    __syncthreads();
    if (tid == 0) {
        int s = 0;
        #pragma unroll
        for (int e = 0; e < 4; e++) { smi[OFF_ST + e] = s; s += smi[OFF_CNT + e]; }
        smi[OFF_ST + 4] = s;
    }
    __syncthreads();
    if (tid < 128 && tid != n) {
        int t = smi[OFF_TY + tid];
        int r = 0;
        for (int j2 = 0; j2 < tid; j2++)
            if (j2 != n && smi[OFF_TY + j2] == t) r++;
        smi[OFF_SIDX + smi[OFF_ST + t] + r] = tid;
    }
    __syncthreads();

    const int  slot   = (pw << 5) + lane;         // 0..127; 127 idle
    const bool active = slot < KNB;
    const int  j = active ? smi[OFF_SIDX + slot] : n;
    const int  e = active ? smi[OFF_TY + j] : 0;

    const float* w0e = sm + OFF_W0 + e * 40;
    const float* b0e = sm + OFF_B0 + e * 40;
    const float* w1q = sm + OFF_W1 + e * E1STR + 16 * qt;
    const float* b1q = sm + OFF_B1 + e * 72 + 16 * qt;
    const float* w2q = sm + OFF_W2 + e * E2STR + 28 * qt;
    const float* b2q = sm + OFF_B2 + e * 136 + 28 * qt;
    const int sz1    = (qt < 2) ? 13 : 12;
    const int tbase1 = (qt < 2) ? 13 * qt : 12 * qt + 2;   // 0,13,26,38
    const int base0  = (qt == 0) ? 0 : 1 + 6 * qt;         // 0,7,13,19
    const int cnt0   = (qt == 0) ? 7 : 6;
    float* h0a = sm + OFF_H0 + slot * 27;
    float* h0b = h0a + H0BUF;
    float* h1a = sm + OFF_X + slot * 51;
    float* h1b = h1a + H1BUF;
    const int barid = 1 + pw;

    for (int bi2 = 0; bi2 < BT / 2; bi2++) {
        const int b0i = blockIdx.y * BT + bi2 * 2;
        __syncthreads();   // X / EA / CS reuse guard
        for (int i = tid; i < 2 * 384; i += THREADS) {
            int bb = i / 384, ii = i % 384;
            sm[OFF_CS + bb * 384 + (ii % 3) * 128 + ii / 3] =
                coords[(size_t)(b0i + bb) * 384 + ii];
        }
        __syncthreads();

        float xa = 0.0f, xb = 0.0f;
        if (active) {
            #pragma unroll
            for (int bb = 0; bb < 2; bb++) {
                const float* cs = sm + OFF_CS + bb * 384;
                float rx = cs[n]       - cs[j];
                float ry = cs[128 + n] - cs[128 + j];
                float rz = cs[256 + n] - cs[256 + j];
                float dinv = rsqrtf(rx * rx + ry * ry + rz * rz);
                float di2 = dinv * dinv;
                if (qt == 0) {
                    float* ea = sm + OFF_EA + bb * 512 + slot * 4;
                    ea[0] = rx * di2; ea[1] = ry * di2; ea[2] = rz * di2; ea[3] = 0.0f;
                }
                if (bb == 0) xa = dinv; else xb = dinv;
            }
            // h0 split across co-warps: qt computes cnt0 entries at base0
            for (int c = 0; c < cnt0; c++) {
                int r = base0 + c;
                float w = w0e[r], bi = b0e[r];
                h0a[r] = tanhx(fmaf(xa, w, bi));
                h0b[r] = tanhx(fmaf(xb, w, bi));
            }
        }
        BARG(barid);   // h0 ready within co-group

        // ---- layer1: quarter outputs, 2 batches; h0 prefetched to regs ----
        {
            float h0ra[25], h0rb[25];
            #pragma unroll
            for (int i = 0; i < 25; i++) { h0ra[i] = h0a[i]; h0rb[i] = h0b[i]; }

            u64 acc[2][8];
            #pragma unroll
            for (int t = 0; t < 4; t++) {
                ulonglong2 bb = *(const ulonglong2*)(b1q + t * 4);
                acc[0][2*t] = bb.x; acc[0][2*t+1] = bb.y;
                acc[1][2*t] = bb.x; acc[1][2*t+1] = bb.y;
            }
            #pragma unroll
            for (int i = 0; i < 25; i++) {
                u64 hda = pack2(h0ra[i], h0ra[i]);
                u64 hdb = pack2(h0rb[i], h0rb[i]);
                const float* wp = w1q + i * 64;
                #pragma unroll
                for (int t = 0; t < 4; t++) {
                    ulonglong2 w = *(const ulonglong2*)(wp + t * 4);
                    acc[0][2*t]   = fma2(w.x, hda, acc[0][2*t]);
                    acc[0][2*t+1] = fma2(w.y, hda, acc[0][2*t+1]);
                    acc[1][2*t]   = fma2(w.x, hdb, acc[1][2*t]);
                    acc[1][2*t+1] = fma2(w.y, hdb, acc[1][2*t+1]);
                }
            }
            if (active) {
                #pragma unroll
                for (int q = 0; q < 7; q++) {
                    float2 va = unpack2(acc[0][q]);
                    float2 vb = unpack2(acc[1][q]);
                    int l0 = 2 * q, l1 = 2 * q + 1;
                    if (l0 < sz1) {
                        int o = tbase1 + l0, r = (o < 25) ? o : o - 25;
                        h1a[o] = tanhx(va.x) + h0a[r];
                        h1b[o] = tanhx(vb.x) + h0b[r];
                    }
                    if (l1 < sz1) {
                        int o = tbase1 + l1, r = (o < 25) ? o : o - 25;
                        h1a[o] = tanhx(va.y) + h0a[r];
                        h1b[o] = tanhx(vb.y) + h0b[r];
                    }
                }
            }
        }
        BARG(barid);   // h1 ready within co-group

        // ---- layer2: quarter (25 outs), 2 batches; h1 chunk-prefetched ----
        float ga[25], gb[25];
        {
            u64 acc[2][14];
            #pragma unroll
            for (int t = 0; t < 7; t++) {
                ulonglong2 bb = *(const ulonglong2*)(b2q + t * 4);
                acc[0][2*t] = bb.x; acc[0][2*t+1] = bb.y;
                acc[1][2*t] = bb.x; acc[1][2*t+1] = bb.y;
            }
            const int CB0[4] = {0, 17, 34, 50};
            #pragma unroll
            for (int c = 0; c < 3; c++) {
                float ha[17], hb[17];
                #pragma unroll
                for (int ii = 0; ii < 17; ii++) {
                    if (CB0[c] + ii < CB0[c + 1]) {
                        ha[ii] = h1a[CB0[c] + ii];
                        hb[ii] = h1b[CB0[c] + ii];
                    }
                }
                #pragma unroll
                for (int ii = 0; ii < 17; ii++) {
                    if (CB0[c] + ii < CB0[c + 1]) {
                        u64 hda = pack2(ha[ii], ha[ii]);
                        u64 hdb = pack2(hb[ii], hb[ii]);
                        const float* wp = w2q + (CB0[c] + ii) * 112;
                        #pragma unroll
                        for (int t = 0; t < 7; t++) {
                            ulonglong2 w = *(const ulonglong2*)(wp + t * 4);
                            acc[0][2*t]   = fma2(w.x, hda, acc[0][2*t]);
                            acc[0][2*t+1] = fma2(w.y, hda, acc[0][2*t+1]);
                            acc[1][2*t]   = fma2(w.x, hdb, acc[1][2*t]);
                            acc[1][2*t+1] = fma2(w.y, hdb, acc[1][2*t+1]);
                        }
                    }
                }
            }
            // residual: m = 25*qt + l -> h1[(25*qt+l) mod 50] = h1[l + 25*(qt&1)]
            const int roff = 25 * (qt & 1);
            #pragma unroll
            for (int q = 0; q < 13; q++) {
                float2 va = unpack2(acc[0][q]);
                float2 vb = unpack2(acc[1][q]);
                int l0 = 2 * q, l1 = 2 * q + 1;
                if (l0 < 25) { ga[l0] = tanhx(va.x) + h1a[roff + l0];
                               gb[l0] = tanhx(vb.x) + h1b[roff + l0]; }
                if (l1 < 25) { ga[l1] = tanhx(va.y) + h1a[roff + l1];
                               gb[l1] = tanhx(vb.y) + h1b[roff + l1]; }
            }
        }
        __syncthreads();   // all h1 reads done; X region becomes G

        #pragma unroll
        for (int bb = 0; bb < 2; bb++) {
            // store this batch's G (registers -> X region)
            if (active) {
                float* grow = sm + OFF_X + slot * GSTR + 25 * qt;
                #pragma unroll
                for (int l = 0; l < 25; l++) grow[l] = bb ? gb[l] : ga[l];
            }
            __syncthreads();

            // U[c][m] = sum_k ea[c][k]*G[k][m]; 4 k-chunks of 32
            const int m  = tid & 127;
            const int kq = tid >> 7;
            float u0 = 0.0f, u1 = 0.0f, u2 = 0.0f;
            if (m < 100) {
                const int kb = kq * 32;
                const int ke = (kq == 3) ? KNB : kb + 32;
                const float* gp = sm + OFF_X + m;
                const float* ep = sm + OFF_EA + bb * 512;
                #pragma unroll 4
                for (int kk = kb; kk < ke; kk++) {
                    float4 ea = *(const float4*)(ep + kk * 4);
                    float g = gp[kk * GSTR];
                    u0 = fmaf(ea.x, g, u0);
                    u1 = fmaf(ea.y, g, u1);
                    u2 = fmaf(ea.z, g, u2);
                }
                sm[OFF_UP + kq * 312 + m]       = u0;
                sm[OFF_UP + kq * 312 + 104 + m] = u1;
                sm[OFF_UP + kq * 312 + 208 + m] = u2;
            }
            __syncthreads();
            float us0 = 0.0f, us1 = 0.0f, us2 = 0.0f;
            if (tid < 100) {
                #pragma unroll
                for (int qq = 0; qq < 4; qq++) {
                    us0 += sm[OFF_UP + qq * 312 + tid];
                    us1 += sm[OFF_UP + qq * 312 + 104 + tid];
                    us2 += sm[OFF_UP + qq * 312 + 208 + tid];
                }
                sm[OFF_US + tid]       = us0;
                sm[OFF_US + 104 + tid] = us1;
                sm[OFF_US + 208 + tid] = us2;
            }
            __syncthreads();
            if (tid < 100) {
                float4 r;
                r.x = us0 * sm[OFF_US + 0] + us1 * sm[OFF_US + 104 + 0] + us2 * sm[OFF_US + 208 + 0];
                r.y = us0 * sm[OFF_US + 1] + us1 * sm[OFF_US + 104 + 1] + us2 * sm[OFF_US + 208 + 1];
                r.z = us0 * sm[OFF_US + 2] + us1 * sm[OFF_US + 104 + 2] + us2 * sm[OFF_US + 208 + 2];
                r.w = us0 * sm[OFF_US + 3] + us1 * sm[OFF_US + 104 + 3] + us2 * sm[OFF_US + 208 + 3];
                *(float4*)(out + ((size_t)(b0i + bb) * NATOM + n) * 400 + tid * 4) = r;
            }
            __syncthreads();   // G reads done before next batch's stores
        }
    }
}

extern "C" void kernel_launch(void* const* d_in, const int* in_sizes, int n_in,
                              void* d_out, int out_size)
{
    (void)in_sizes; (void)n_in; (void)out_size;
    const float* coords = (const float*)d_in[0];
    const int*   types  = (const int*)d_in[1];
    const float* W0g = (const float*)d_in[2];
    const float* B0g = (const float*)d_in[3];
    const float* W1g = (const float*)d_in[4];
    const float* B1g = (const float*)d_in[5];
    const float* W2g = (const float*)d_in[6];
    const float* B2g = (const float*)d_in[7];
    float* out = (float*)d_out;

    cudaFuncSetAttribute(feat_kernel, cudaFuncAttributeMaxDynamicSharedMemorySize, SMEM_BYTES);

    dim3 grid(NATOM, NBATCH / BT);   // (128, 8)
    feat_kernel<<<grid, THREADS, SMEM_BYTES>>>(coords, types,
                                               W0g, B0g, W1g, B1g, W2g, B2g, out);
}